// round 17
// baseline (speedup 1.0000x reference)
#include <cuda_runtime.h>
#include <cuda_bf16.h>
#include <cstdint>

#define N_ROWS 32768
#define K_CODES 8192
#define D_DIM 512

#define BM 128
#define BN 128
#define BKE 64              // bf16 k-elems per tile
#define STAGES 3
#define NCHUNKS 64          // K_CODES / BN
#define KSPLIT 8            // chunk-range split for load balance (grid 2048)
#define KITERS 8            // D_DIM / BKE
#define RSU 36              // row stride in uint32 (64/2 + 4 pad) = 144 B
#define MARGIN 1.2e-3f
#define NSHARDS 64
#define SHARD_CAP 65536
#define FLT_MAX_BITS 0x7f7fffff

#define ZPAIRS (N_ROWS * D_DIM / 2)
#define EPAIRS (K_CODES * D_DIM / 2)

// ---------------- scratch (static __device__, no allocs) ----------------
__device__ float  g_znorm[N_ROWS];
__device__ float  g_enorm[K_CODES];
__device__ uint32_t g_zbf[ZPAIRS];   // packed bf16x2
__device__ uint32_t g_ebf[EPAIRS];
__device__ int    g_bound[N_ROWS];   // cross-CTA approx-distance bound (fp32 bits)
__device__ unsigned long long g_best[N_ROWS];
__device__ int    g_cand[NSHARDS][SHARD_CAP];
__device__ float  g_cand_d[NSHARDS][SHARD_CAP];   // approx distance at push time
__device__ int    g_ncand[NSHARDS];
__device__ double g_rowpart[N_ROWS];

// ---------------- helpers ----------------
__device__ __forceinline__ uint32_t smem_u32(const void* p) {
    uint32_t a;
    asm("{ .reg .u64 t; cvta.to.shared.u64 t, %1; cvt.u32.u64 %0, t; }" : "=r"(a) : "l"(p));
    return a;
}
__device__ __forceinline__ void cpasync16(uint32_t dst, const void* src) {
    asm volatile("cp.async.cg.shared.global [%0], [%1], 16;" :: "r"(dst), "l"(src));
}
#define CP_COMMIT() asm volatile("cp.async.commit_group;" ::: "memory")
#define CP_WAITG1() asm volatile("cp.async.wait_group 1;" ::: "memory")
#define CP_WAIT0()  asm volatile("cp.async.wait_group 0;" ::: "memory")

#define LDSM_X4(r0, r1, r2, r3, addr) \
    asm volatile("ldmatrix.sync.aligned.m8n8.x4.shared.b16 {%0,%1,%2,%3}, [%4];" \
        : "=r"(r0), "=r"(r1), "=r"(r2), "=r"(r3) : "r"(addr))

// m16n8k16 bf16 HMMA (sm_80 base feature)
__device__ __forceinline__ void mma_bf16(float* d, const uint32_t* a, const uint32_t* b) {
    asm volatile("mma.sync.aligned.m16n8k16.row.col.f32.bf16.bf16.f32 "
        "{%0,%1,%2,%3}, {%4,%5,%6,%7}, {%8,%9}, {%0,%1,%2,%3};"
        : "+f"(d[0]), "+f"(d[1]), "+f"(d[2]), "+f"(d[3])
        : "r"(a[0]), "r"(a[1]), "r"(a[2]), "r"(a[3]), "r"(b[0]), "r"(b[1]));
}

// ---------------------------------------------------------------------------
// Fused: scratch init + bf16 convert + row norms in one pass.
// float4 loads (16B/lane) + uint2 stores (8B/lane): half the LSU ops of the
// float2 version, same numeric order.
// ---------------------------------------------------------------------------
__global__ void prep_kernel(const float* __restrict__ Z, const float* __restrict__ E) {
    const int gtid = blockIdx.x * blockDim.x + threadIdx.x;
    if (gtid < N_ROWS) {
        g_best[gtid]  = 0xFFFFFFFFFFFFFFFFULL;
        g_bound[gtid] = FLT_MAX_BITS;
    }
    if (gtid < NSHARDS) g_ncand[gtid] = 0;

    int gw = gtid >> 5;
    int lane = threadIdx.x & 31;
    if (gw >= N_ROWS + K_CODES) return;
    const float4* src;
    uint2* dst;
    if (gw < N_ROWS) {
        src = reinterpret_cast<const float4*>(Z + (size_t)gw * D_DIM);
        dst = reinterpret_cast<uint2*>(g_zbf + (size_t)gw * (D_DIM / 2));
    } else {
        int r = gw - N_ROWS;
        src = reinterpret_cast<const float4*>(E + (size_t)r * D_DIM);
        dst = reinterpret_cast<uint2*>(g_ebf + (size_t)r * (D_DIM / 2));
    }
    float acc = 0.0f;
    #pragma unroll
    for (int j = 0; j < 4; j++) {
        float4 v = src[j * 32 + lane];
        acc = fmaf(v.x, v.x, acc);
        acc = fmaf(v.y, v.y, acc);
        acc = fmaf(v.z, v.z, acc);
        acc = fmaf(v.w, v.w, acc);
        __nv_bfloat162 b0 = __floats2bfloat162_rn(v.x, v.y);
        __nv_bfloat162 b1 = __floats2bfloat162_rn(v.z, v.w);
        dst[j * 32 + lane] = make_uint2(*reinterpret_cast<uint32_t*>(&b0),
                                        *reinterpret_cast<uint32_t*>(&b1));
    }
    #pragma unroll
    for (int o = 16; o > 0; o >>= 1) acc += __shfl_down_sync(0xffffffffu, acc, o);
    if (lane == 0) {
        if (gw < N_ROWS) g_znorm[gw] = acc;
        else             g_enorm[gw - N_ROWS] = acc;
    }
}

// ---------------------------------------------------------------------------
// bf16 m16n8k16 GEMM + running per-row best + margin candidate push.
// 128x128 CTA, warp 64x32, 8 warps, 2 CTAs/SM, 3-stage cp.async, KSPLIT=8.
// Cross-CTA atomicMin bound pruning; distances computed ONCE per chunk
// (pass 1 overwrites the dead accumulators in place; pass 2 reads them).
// ---------------------------------------------------------------------------
__global__ __launch_bounds__(256, 2)
void vq_mma_kernel(const float* __restrict__, const float* __restrict__) {
    extern __shared__ uint32_t sm_u[];
    int* s_rowbest = reinterpret_cast<int*>(sm_u + STAGES * 2 * BM * RSU);

    const int tid = threadIdx.x;
    const int wid = tid >> 5;
    const int l   = tid & 31;
    const int warp_m = wid >> 2;        // 0..1
    const int warp_n = wid & 3;         // 0..3
    const int l4 = l >> 2;              // 0..7
    const int kc = l & 3;               // 0..3
    const int row0 = (blockIdx.x >> 3) * BM;
    const int c0   = (blockIdx.x & 7) * (NCHUNKS / KSPLIT);
    const int shard = blockIdx.x & (NSHARDS - 1);

    const uint32_t sm_base  = smem_u32(sm_u);
    const int      stage_u  = 2 * BM * RSU;                 // u32 per stage
    const uint32_t stage_b  = (uint32_t)stage_u * 4;
    const uint32_t eoff_b   = (uint32_t)(BM * RSU) * 4;

    const uint32_t a_off = (uint32_t)((warp_m * 64 + (l & 15)) * RSU * 4 + ((l >> 4) * 16));
    const uint32_t b_off = (uint32_t)((warp_n * 32 + (l & 7) + ((l >> 4) << 3)) * RSU * 4
                                      + (((l >> 3) & 1) * 16)) + eoff_b;

    if (tid < BM) s_rowbest[tid] = FLT_MAX_BITS;

    float zn[8];
    #pragma unroll
    for (int mi = 0; mi < 4; mi++)
        #pragma unroll
        for (int hi = 0; hi < 2; hi++)
            zn[mi * 2 + hi] = g_znorm[row0 + warp_m * 64 + mi * 16 + hi * 8 + l4];

    __syncthreads();

    const int DP = D_DIM / 2;   // global row stride in pairs

    for (int c = c0; c < c0 + NCHUNKS / KSPLIT; c++) {
        float acc[4][4][4];
        #pragma unroll
        for (int mi = 0; mi < 4; mi++)
            #pragma unroll
            for (int ni = 0; ni < 4; ni++)
                #pragma unroll
                for (int r = 0; r < 4; r++) acc[mi][ni][r] = 0.0f;

        const uint32_t* Zg0 = g_zbf + (size_t)row0 * DP;
        const uint32_t* Eg0 = g_ebf + (size_t)(c * BN) * DP;

        #pragma unroll
        for (int pre = 0; pre < 2; pre++) {
            const int kp = pre * (BKE / 2);
            const uint32_t zb = sm_base + (uint32_t)pre * stage_b;
            const uint32_t eb = zb + eoff_b;
            #pragma unroll
            for (int i = 0; i < 4; i++) {
                int u = tid + i * 256, r = u >> 3, s = u & 7;
                cpasync16(zb + r * (RSU * 4) + s * 16, Zg0 + (size_t)r * DP + kp + s * 4);
                cpasync16(eb + r * (RSU * 4) + s * 16, Eg0 + (size_t)r * DP + kp + s * 4);
            }
            CP_COMMIT();
        }

        #pragma unroll
        for (int it = 0; it < KITERS; it++) {
            if (it == KITERS - 1) { CP_WAIT0(); } else { CP_WAITG1(); }
            __syncthreads();
            if (it + 2 < KITERS) {
                const int st = (it + 2) % STAGES;
                const int kp = (it + 2) * (BKE / 2);
                const uint32_t zb = sm_base + (uint32_t)st * stage_b;
                const uint32_t eb = zb + eoff_b;
                #pragma unroll
                for (int i = 0; i < 4; i++) {
                    int u = tid + i * 256, r = u >> 3, s = u & 7;
                    cpasync16(zb + r * (RSU * 4) + s * 16, Zg0 + (size_t)r * DP + kp + s * 4);
                    cpasync16(eb + r * (RSU * 4) + s * 16, Eg0 + (size_t)r * DP + kp + s * 4);
                }
                CP_COMMIT();
            }
            const uint32_t stg = sm_base + (uint32_t)(it % STAGES) * stage_b;
            const uint32_t abase = stg + a_off;
            const uint32_t bbase = stg + b_off;
            #pragma unroll
            for (int ks = 0; ks < 4; ks++) {
                uint32_t a[4][4], b[4][2];
                #pragma unroll
                for (int mi = 0; mi < 4; mi++)
                    LDSM_X4(a[mi][0], a[mi][1], a[mi][2], a[mi][3],
                            abase + mi * (16 * RSU * 4) + ks * 32);
                #pragma unroll
                for (int np = 0; np < 2; np++)
                    LDSM_X4(b[2 * np][0], b[2 * np][1], b[2 * np + 1][0], b[2 * np + 1][1],
                            bbase + np * (16 * RSU * 4) + ks * 32);
                #pragma unroll
                for (int mi = 0; mi < 4; mi++)
                    #pragma unroll
                    for (int ni = 0; ni < 4; ni++)
                        mma_bf16(acc[mi][ni], a[mi], b[ni]);
            }
        }

        // ---------- epilogue pass 1: distances (in place) + per-row min ----------
        const int colg0 = c * BN + warp_n * 32 + kc * 2;
        float dmin[8];
        #pragma unroll
        for (int i = 0; i < 8; i++) dmin[i] = 3.4028235e38f;
        #pragma unroll
        for (int ni = 0; ni < 4; ni++) {
            float en0 = __ldg(&g_enorm[colg0 + ni * 8]);
            float en1 = __ldg(&g_enorm[colg0 + ni * 8 + 1]);
            #pragma unroll
            for (int mi = 0; mi < 4; mi++) {
                float d0 = (zn[mi * 2] + en0)     - 2.0f * acc[mi][ni][0];
                float d1 = (zn[mi * 2] + en1)     - 2.0f * acc[mi][ni][1];
                float d2 = (zn[mi * 2 + 1] + en0) - 2.0f * acc[mi][ni][2];
                float d3 = (zn[mi * 2 + 1] + en1) - 2.0f * acc[mi][ni][3];
                acc[mi][ni][0] = d0; acc[mi][ni][1] = d1;   // accs are dead: keep d
                acc[mi][ni][2] = d2; acc[mi][ni][3] = d3;
                dmin[mi * 2]     = fminf(dmin[mi * 2], fminf(d0, d1));
                dmin[mi * 2 + 1] = fminf(dmin[mi * 2 + 1], fminf(d2, d3));
            }
        }
        #pragma unroll
        for (int i = 0; i < 8; i++) {
            dmin[i] = fminf(dmin[i], __shfl_xor_sync(0xffffffffu, dmin[i], 1));
            dmin[i] = fminf(dmin[i], __shfl_xor_sync(0xffffffffu, dmin[i], 2));
        }
        if (kc == 0) {
            #pragma unroll
            for (int mi = 0; mi < 4; mi++) {
                const int rl0 = warp_m * 64 + mi * 16 + l4;
                const int rl1 = rl0 + 8;
                int b0 = __float_as_int(dmin[mi * 2]);
                int b1 = __float_as_int(dmin[mi * 2 + 1]);
                int og0 = atomicMin(&g_bound[row0 + rl0], b0);
                int og1 = atomicMin(&g_bound[row0 + rl1], b1);
                atomicMin(&s_rowbest[rl0], min(og0, b0));
                atomicMin(&s_rowbest[rl1], min(og1, b1));
            }
        }
        __syncthreads();

        // ---------- epilogue pass 2: margin push from stored distances ----------
        #pragma unroll
        for (int mi = 0; mi < 4; mi++) {
            const int rl0 = warp_m * 64 + mi * 16 + l4;
            const int rl1 = rl0 + 8;
            const float b0 = __int_as_float(s_rowbest[rl0]) + MARGIN;
            const float b1 = __int_as_float(s_rowbest[rl1]) + MARGIN;
            #pragma unroll
            for (int ni = 0; ni < 4; ni++) {
                float d0 = acc[mi][ni][0], d1 = acc[mi][ni][1];
                float d2 = acc[mi][ni][2], d3 = acc[mi][ni][3];
                if (d0 < b0) { int p = atomicAdd(&g_ncand[shard], 1);
                    if (p < SHARD_CAP) { g_cand[shard][p] = ((row0 + rl0) << 13) | (colg0 + ni * 8);
                                         g_cand_d[shard][p] = d0; } }
                if (d1 < b0) { int p = atomicAdd(&g_ncand[shard], 1);
                    if (p < SHARD_CAP) { g_cand[shard][p] = ((row0 + rl0) << 13) | (colg0 + ni * 8 + 1);
                                         g_cand_d[shard][p] = d1; } }
                if (d2 < b1) { int p = atomicAdd(&g_ncand[shard], 1);
                    if (p < SHARD_CAP) { g_cand[shard][p] = ((row0 + rl1) << 13) | (colg0 + ni * 8);
                                         g_cand_d[shard][p] = d2; } }
                if (d3 < b1) { int p = atomicAdd(&g_ncand[shard], 1);
                    if (p < SHARD_CAP) { g_cand[shard][p] = ((row0 + rl1) << 13) | (colg0 + ni * 8 + 1);
                                         g_cand_d[shard][p] = d3; } }
            }
        }
    }
}

// ---------------------------------------------------------------------------
// Exact fp32 refinement with FINAL-bound pre-pruning.
// ---------------------------------------------------------------------------
__global__ void refine_kernel(const float* __restrict__ Z, const float* __restrict__ E) {
    const int nwarps = (gridDim.x * blockDim.x) >> 5;
    const int gw     = (blockIdx.x * blockDim.x + threadIdx.x) >> 5;
    const int lane   = threadIdx.x & 31;

    for (int s = 0; s < NSHARDS; s++) {
        int n = g_ncand[s];
        if (n > SHARD_CAP) n = SHARD_CAP;
        for (int i = gw; i < n; i += nwarps) {
            int cd  = g_cand[s][i];
            int row = cd >> 13;
            int idx = cd & (K_CODES - 1);
            float dhat  = g_cand_d[s][i];
            float bound = __int_as_float(g_bound[row]);
            if (dhat > bound + MARGIN) continue;

            const float4* z4 = reinterpret_cast<const float4*>(Z + (size_t)row * D_DIM);
            const float4* e4 = reinterpret_cast<const float4*>(E + (size_t)idx * D_DIM);
            float4 zv[4], ev[4];
            #pragma unroll
            for (int j = 0; j < 4; j++) {
                zv[j] = z4[j * 32 + lane];
                ev[j] = e4[j * 32 + lane];
            }
            float dot = 0.0f;
            #pragma unroll
            for (int j = 0; j < 4; j++) {
                dot = fmaf(zv[j].x, ev[j].x, dot);
                dot = fmaf(zv[j].y, ev[j].y, dot);
                dot = fmaf(zv[j].z, ev[j].z, dot);
                dot = fmaf(zv[j].w, ev[j].w, dot);
            }
            #pragma unroll
            for (int o = 16; o > 0; o >>= 1) dot += __shfl_down_sync(0xffffffffu, dot, o);
            if (lane == 0) {
                float d = (g_znorm[row] + g_enorm[idx]) - 2.0f * dot;
                unsigned long long key = ((unsigned long long)__float_as_uint(d) << 32) | (unsigned)idx;
                atomicMin(&g_best[row], key);
            }
        }
    }
}

// ---------------------------------------------------------------------------
// Gather: one warp per row; fp32 per-row loss partial (no FP64 chain).
// ---------------------------------------------------------------------------
__global__ void gather_kernel(const float* __restrict__ Z, const float* __restrict__ E,
                              float* __restrict__ out, int out_size) {
    const int row  = blockIdx.x * 8 + (threadIdx.x >> 5);
    const int lane = threadIdx.x & 31;
    int idx = (int)(g_best[row] & 0xFFFFFFFFull) & (K_CODES - 1);
    const float4* e4 = reinterpret_cast<const float4*>(E + (size_t)idx * D_DIM);
    const float4* z4 = reinterpret_cast<const float4*>(Z + (size_t)row * D_DIM);
    float4* o4 = reinterpret_cast<float4*>(out + (size_t)row * D_DIM);

    float sp[4];
    #pragma unroll
    for (int j = 0; j < 4; j++) {
        float4 q = e4[j * 32 + lane], zc = z4[j * 32 + lane], dq, o;
        dq.x = q.x - zc.x; dq.y = q.y - zc.y; dq.z = q.z - zc.z; dq.w = q.w - zc.w;
        o.x = zc.x + dq.x; o.y = zc.y + dq.y; o.z = zc.z + dq.z; o.w = zc.w + dq.w;
        o4[j * 32 + lane] = o;
        sp[j] = fmaf(dq.x, dq.x, fmaf(dq.y, dq.y, fmaf(dq.z, dq.z, dq.w * dq.w)));
    }
    float s = (sp[0] + sp[1]) + (sp[2] + sp[3]);
    #pragma unroll
    for (int o2 = 16; o2 > 0; o2 >>= 1) s += __shfl_down_sync(0xffffffffu, s, o2);
    if (lane == 0) {
        g_rowpart[row] = (double)s;
        if (out_size >= N_ROWS * D_DIM + 1 + N_ROWS)
            out[(size_t)N_ROWS * D_DIM + 1 + row] = (float)idx;
    }
}

__global__ void loss_kernel(float* __restrict__ out, int out_size) {
    __shared__ double sh[1024];
    int t = threadIdx.x;
    double s = 0.0;
    for (int i = t; i < N_ROWS; i += 1024) s += g_rowpart[i];
    sh[t] = s;
    __syncthreads();
    for (int o = 512; o > 0; o >>= 1) { if (t < o) sh[t] += sh[t + o]; __syncthreads(); }
    if (t == 0 && out_size >= N_ROWS * D_DIM + 1) {
        double m = sh[0] / ((double)N_ROWS * (double)D_DIM);
        out[(size_t)N_ROWS * D_DIM] = (float)(1.25 * m);
    }
}

// ---------------------------------------------------------------------------
extern "C" void kernel_launch(void* const* d_in, const int* in_sizes, int n_in,
                              void* d_out, int out_size) {
    const float* z = (const float*)d_in[0];
    const float* e = (const float*)d_in[1];
    if (n_in >= 2 && in_sizes[0] == K_CODES * D_DIM && in_sizes[1] == N_ROWS * D_DIM) {
        const float* tmp = z; z = e; e = tmp;
    }
    float* out = (float*)d_out;

    const int smem_bytes = STAGES * 2 * BM * RSU * 4 + BM * 4;   // 111104
    cudaFuncSetAttribute(vq_mma_kernel, cudaFuncAttributeMaxDynamicSharedMemorySize, smem_bytes);

    int prep_blocks = ((N_ROWS + K_CODES) * 32 + 255) / 256;     // one warp per row
    prep_kernel<<<prep_blocks, 256>>>(z, e);
    vq_mma_kernel<<<(N_ROWS / BM) * KSPLIT, 256, smem_bytes>>>(z, e);
    refine_kernel<<<1024, 256>>>(z, e);
    gather_kernel<<<N_ROWS / 8, 256>>>(z, e, out, out_size);
    loss_kernel<<<1, 1024>>>(out, out_size);
}